// round 10
// baseline (speedup 1.0000x reference)
#include <cuda_runtime.h>
#include <cuda_bf16.h>
#include <cstdint>

// ---------------------------------------------------------------------------
// Problem constants
// ---------------------------------------------------------------------------
#define B_DIM 4096
#define H_DIM 1024
#define N_GATES 4096       // 4*H
#define K_DIM  2048        // D + H

// GEMM tiling (int8 IMMA path)
#define BM 128
#define BN 64
#define BK 64              // 64 int8 = 64 B rows; 2 x k32 IMMA steps per stage
#define STAGES 4
#define NT (K_DIM / BK)    // 32 k-tiles
#define NTHREADS 256

// smem per stage: Ahi/Alo 128x64B + Bhi/Blo 64x64B = 24576 B
#define A_TILE_BYTES 8192
#define B_TILE_BYTES 4096
#define STAGE_BYTES (2 * A_TILE_BYTES + 2 * B_TILE_BYTES)   // 24576
#define OFF_ALO A_TILE_BYTES
#define OFF_BHI (2 * A_TILE_BYTES)
#define OFF_BLO (2 * A_TILE_BYTES + B_TILE_BYTES)
#define SMEM_TOTAL (STAGES * STAGE_BYTES)                   // 98304 -> 2 CTAs/SM

#define QMAX 32512.0f      // 16-bit fixed-point range (keeps ah in [-127,127])

// ---------------------------------------------------------------------------
// Scratch (device globals). gB*/gSB/gBias are GATE-INTERLEAVED: n' = j*4+g.
// ---------------------------------------------------------------------------
__device__ int8_t gAhi[(size_t)B_DIM * K_DIM];
__device__ int8_t gAlo[(size_t)B_DIM * K_DIM];
__device__ int8_t gBhi[(size_t)N_GATES * K_DIM];
__device__ int8_t gBlo[(size_t)N_GATES * K_DIM];
__device__ float gSA[B_DIM];
__device__ float gSB[N_GATES];
__device__ float gBias[N_GATES];

// ---------------------------------------------------------------------------
// PTX helpers (sm_80+ portable)
// ---------------------------------------------------------------------------
__device__ __forceinline__ uint32_t smem_u32(const void* p) {
    uint32_t a;
    asm("{ .reg .u64 t; cvta.to.shared.u64 t, %1; cvt.u32.u64 %0, t; }" : "=r"(a) : "l"(p));
    return a;
}

#define CP_ASYNC16(dst, src) \
    asm volatile("cp.async.cg.shared.global [%0], [%1], 16;" \
                 :: "r"(dst), "l"(src) : "memory")
#define CP_COMMIT() asm volatile("cp.async.commit_group;" ::: "memory")
#define CP_WAIT(n)  asm volatile("cp.async.wait_group %0;" :: "n"(n) : "memory")

#define LDSM_X4(r, addr) \
    asm volatile("ldmatrix.sync.aligned.m8n8.x4.shared.b16 {%0,%1,%2,%3}, [%4];" \
                 : "=r"((r)[0]), "=r"((r)[1]), "=r"((r)[2]), "=r"((r)[3]) : "r"(addr))

__device__ __forceinline__ void imma(int* d, const uint32_t* a, uint32_t b0, uint32_t b1) {
    asm volatile(
        "mma.sync.aligned.m16n8k32.row.col.s32.s8.s8.s32 "
        "{%0,%1,%2,%3}, {%4,%5,%6,%7}, {%8,%9}, {%0,%1,%2,%3};"
        : "+r"(d[0]), "+r"(d[1]), "+r"(d[2]), "+r"(d[3])
        : "r"(a[0]), "r"(a[1]), "r"(a[2]), "r"(a[3]), "r"(b0), "r"(b1));
}

__device__ __forceinline__ float sigmoidf_(float v) {
    return 1.0f / (1.0f + __expf(-v));
}

// ---------------------------------------------------------------------------
// Row quantization kernel.
//   blocks [0, 4096):     A rows  (x|h0)     -> gAhi/gAlo, gSA
//   blocks [4096, 8192):  B rows  (wih|whh)  -> gBhi/gBlo, gSB (permuted j*4+g)
//   blocks [8192, 8208):  permuted bias sum
// One block per row: 256 threads x 8 floats; rowmax reduce; 16-bit split.
// ---------------------------------------------------------------------------
__global__ __launch_bounds__(256)
void quantize_rows(const float* __restrict__ x,   const float* __restrict__ h0,
                   const float* __restrict__ wih, const float* __restrict__ whh,
                   const float* __restrict__ b_ih, const float* __restrict__ b_hh)
{
    const int bid = blockIdx.x;
    const int tid = threadIdx.x;

    if (bid >= 8192) {                        // bias
        const int np = (bid - 8192) * 256 + tid;         // 0..4095
        const int r = ((np & 3) << 10) | (np >> 2);      // orig row g*1024+j
        gBias[np] = b_ih[r] + b_hh[r];
        return;
    }

    const bool isA = (bid < 4096);
    const int row  = isA ? bid : bid - 4096;             // output row
    const int srow = isA ? row : ((row & 3) << 10) | (row >> 2);
    const float* s0 = isA ? x  : wih;
    const float* s1 = isA ? h0 : whh;

    // load 8 floats (two float4: one from each source half)
    float4 va = *reinterpret_cast<const float4*>(s0 + (size_t)srow * 1024 + tid * 4);
    float4 vb = *reinterpret_cast<const float4*>(s1 + (size_t)srow * 1024 + tid * 4);
    float f[8] = {va.x, va.y, va.z, va.w, vb.x, vb.y, vb.z, vb.w};

    float m = 0.0f;
    #pragma unroll
    for (int i = 0; i < 8; i++) m = fmaxf(m, fabsf(f[i]));

    __shared__ float sred[8];
    #pragma unroll
    for (int o = 16; o > 0; o >>= 1) m = fmaxf(m, __shfl_xor_sync(0xffffffffu, m, o));
    if ((tid & 31) == 0) sred[tid >> 5] = m;
    __syncthreads();
    if (tid == 0) {
        float mm = sred[0];
        #pragma unroll
        for (int i = 1; i < 8; i++) mm = fmaxf(mm, sred[i]);
        sred[0] = mm;
    }
    __syncthreads();
    const float bmax = sred[0];
    const float inv = (bmax > 0.0f) ? (QMAX / bmax) : 0.0f;

    signed char hq[8], lq[8];
    #pragma unroll
    for (int i = 0; i < 8; i++) {
        const int v = __float2int_rn(f[i] * inv);
        const int ah = (v + 128) >> 8;            // nearest, ah in [-127,127]
        const int al = v - (ah << 8);             // al in [-128,127]
        hq[i] = (signed char)ah;
        lq[i] = (signed char)al;
    }
    char4 hi0 = make_char4(hq[0], hq[1], hq[2], hq[3]);
    char4 hi1 = make_char4(hq[4], hq[5], hq[6], hq[7]);
    char4 lo0 = make_char4(lq[0], lq[1], lq[2], lq[3]);
    char4 lo1 = make_char4(lq[4], lq[5], lq[6], lq[7]);

    int8_t* hi = isA ? gAhi : gBhi;
    int8_t* lo = isA ? gAlo : gBlo;
    const size_t o0 = (size_t)row * K_DIM + tid * 4;
    *reinterpret_cast<char4*>(hi + o0)        = hi0;
    *reinterpret_cast<char4*>(hi + o0 + 1024) = hi1;
    *reinterpret_cast<char4*>(lo + o0)        = lo0;
    *reinterpret_cast<char4*>(lo + o0 + 1024) = lo1;

    if (tid == 0) {
        const float s = bmax / QMAX;
        if (isA) gSA[row] = s; else gSB[row] = s;
    }
}

// ---------------------------------------------------------------------------
// Fused int8 GEMM + LSTM epilogue.
//   gates = sA*sB*(2^16 * Ah*Bh^T + 2^8 * (Ah*Bl^T + Al*Bh^T))  (permuted cols)
//   then per (b,j): c = sig(f)*c0 + sig(i)*tanh(g); h = sig(o)*tanh(c)
// SMEM: rows x 4 16B chunks, chunk' = chunk ^ ((row>>1)&3) (conflict-free).
// ---------------------------------------------------------------------------
__global__ __launch_bounds__(NTHREADS, 2)
void lstm_gemm_fused(const float* __restrict__ c0, float* __restrict__ out)
{
    extern __shared__ char smem[];
    const uint32_t sb = smem_u32(smem);
    const int tid  = threadIdx.x;
    const int wid  = tid >> 5;
    const int lane = tid & 31;
    const int warp_m = wid >> 1;    // 0..3
    const int warp_n = wid & 1;     // 0..1

    const int bm = blockIdx.y * BM;
    const int bn = blockIdx.x * BN;

    int acc_hh[2][4][4], acc_mid[2][4][4];
    #pragma unroll
    for (int mt = 0; mt < 2; mt++)
        #pragma unroll
        for (int nt = 0; nt < 4; nt++)
            #pragma unroll
            for (int j = 0; j < 4; j++) { acc_hh[mt][nt][j] = 0; acc_mid[mt][nt][j] = 0; }

    // ---- ldmatrix addressing (s8 k32 fragments; x4 tile order = frag order) --
    const int a_row = warp_m * 32 + (lane & 15);
    const int s_a   = (a_row >> 1) & 3;
    const int a_c0  = lane >> 4;                          // 16B chunk within 32B k-step
    const int b_row = warp_n * 32 + (lane & 15);
    const int s_b   = (b_row >> 1) & 3;
    const int b_c0  = lane >> 4;

    // ---- cp.async addressing ----
    const int r0 = tid >> 2;                 // 0..63
    const int cc = tid & 3;                  // 16B chunk
    const uint32_t dstoff = (uint32_t)(r0 * 64 + ((cc ^ ((r0 >> 1) & 3)) << 4));
    const int8_t* pAhi = gAhi + (size_t)(bm + r0) * K_DIM + cc * 16;
    const int8_t* pAlo = gAlo + (size_t)(bm + r0) * K_DIM + cc * 16;
    const int8_t* pBhi = gBhi + (size_t)(bn + r0) * K_DIM + cc * 16;
    const int8_t* pBlo = gBlo + (size_t)(bn + r0) * K_DIM + cc * 16;
    const size_t HSTEP = (size_t)64 * K_DIM;   // +64 rows (A tile second half)

    #define LOAD_STAGE(bufidx, k0) do {                                         \
        const uint32_t s_ = sb + (bufidx) * STAGE_BYTES + dstoff;               \
        CP_ASYNC16(s_,                      pAhi + (k0));                       \
        CP_ASYNC16(s_ + 4096,               pAhi + (k0) + HSTEP);               \
        CP_ASYNC16(s_ + OFF_ALO,            pAlo + (k0));                       \
        CP_ASYNC16(s_ + OFF_ALO + 4096,     pAlo + (k0) + HSTEP);               \
        CP_ASYNC16(s_ + OFF_BHI,            pBhi + (k0));                       \
        CP_ASYNC16(s_ + OFF_BLO,            pBlo + (k0));                       \
    } while (0)

    // prologue: stages 0,1,2
    LOAD_STAGE(0, 0);
    CP_COMMIT();
    LOAD_STAGE(1, BK);
    CP_COMMIT();
    LOAD_STAGE(2, 2 * BK);
    CP_COMMIT();

    for (int t = 0; t < NT; t++) {
        CP_WAIT(2);
        __syncthreads();
        if (t + 3 < NT)
            LOAD_STAGE((t + 3) & 3, (t + 3) * BK);
        CP_COMMIT();

        const uint32_t stage = sb + (t & 3) * STAGE_BYTES;
        #pragma unroll
        for (int ks = 0; ks < 2; ks++) {     // two k32 steps per 64B stage row
            uint32_t a_hi[2][4], a_lo[2][4];
            const int ca = ((ks * 2 + a_c0) ^ s_a) << 4;
            #pragma unroll
            for (int mt = 0; mt < 2; mt++) {
                const uint32_t aa = stage + (a_row + mt * 16) * 64 + ca;
                LDSM_X4(a_hi[mt], aa);
                LDSM_X4(a_lo[mt], aa + OFF_ALO);
            }
            const int cb = ((ks * 2 + b_c0) ^ s_b) << 4;
            #pragma unroll
            for (int g = 0; g < 2; g++) {    // n16 groups
                uint32_t b_hi[4], b_lo[4];
                const uint32_t ba = stage + OFF_BHI + (b_row + g * 16) * 64 + cb;
                LDSM_X4(b_hi, ba);
                LDSM_X4(b_lo, ba + B_TILE_BYTES);
                // b regs: {n 0-7 b0, n 8-15 b0, n 0-7 b1, n 8-15 b1} per x4 order
                #pragma unroll
                for (int mt = 0; mt < 2; mt++)
                    #pragma unroll
                    for (int h = 0; h < 2; h++)
                        imma(acc_hh[mt][g * 2 + h],  a_hi[mt], b_hi[h], b_hi[2 + h]);
                #pragma unroll
                for (int mt = 0; mt < 2; mt++)
                    #pragma unroll
                    for (int h = 0; h < 2; h++)
                        imma(acc_mid[mt][g * 2 + h], a_hi[mt], b_lo[h], b_lo[2 + h]);
                #pragma unroll
                for (int mt = 0; mt < 2; mt++)
                    #pragma unroll
                    for (int h = 0; h < 2; h++)
                        imma(acc_mid[mt][g * 2 + h], a_lo[mt], b_hi[h], b_hi[2 + h]);
            }
        }
    }

    // ---- fused LSTM epilogue ----
    const int q = lane & 3;
    const bool is_if = ((q & 1) == 0);

    float bsum[4][2], sbv[4][2];
    #pragma unroll
    for (int nt = 0; nt < 4; nt++) {
        const int c = bn + warp_n * 32 + nt * 8 + q * 2;
        bsum[nt][0] = gBias[c];
        bsum[nt][1] = gBias[c + 1];
        sbv[nt][0]  = gSB[c];
        sbv[nt][1]  = gSB[c + 1];
    }

    #pragma unroll
    for (int mt = 0; mt < 2; mt++) {
        const int r = bm + warp_m * 32 + mt * 16 + (lane >> 2);
        const float sa0 = gSA[r];
        const float sa1 = gSA[r + 8];
        #pragma unroll
        for (int nt = 0; nt < 4; nt++) {
            const float g0 = 65536.0f * __int2float_rn(acc_hh[mt][nt][0])
                           +   256.0f * __int2float_rn(acc_mid[mt][nt][0]);
            const float g1 = 65536.0f * __int2float_rn(acc_hh[mt][nt][1])
                           +   256.0f * __int2float_rn(acc_mid[mt][nt][1]);
            const float g2 = 65536.0f * __int2float_rn(acc_hh[mt][nt][2])
                           +   256.0f * __int2float_rn(acc_mid[mt][nt][2]);
            const float g3 = 65536.0f * __int2float_rn(acc_hh[mt][nt][3])
                           +   256.0f * __int2float_rn(acc_mid[mt][nt][3]);
            float v0 = sa0 * sbv[nt][0] * g0 + bsum[nt][0];
            float v1 = sa0 * sbv[nt][1] * g1 + bsum[nt][1];
            float v2 = sa1 * sbv[nt][0] * g2 + bsum[nt][0];
            float v3 = sa1 * sbv[nt][1] * g3 + bsum[nt][1];

            const float o0 = __shfl_xor_sync(0xffffffffu, v0, 1);
            const float o1 = __shfl_xor_sync(0xffffffffu, v1, 1);
            const float o2 = __shfl_xor_sync(0xffffffffu, v2, 1);
            const float o3 = __shfl_xor_sync(0xffffffffu, v3, 1);

            const float gi0 = is_if ? v0 : o0;
            const float gf0 = is_if ? v1 : o1;
            const float gg0 = is_if ? o0 : v0;
            const float go0 = is_if ? o1 : v1;
            const float gi1 = is_if ? v2 : o2;
            const float gf1 = is_if ? v3 : o3;
            const float gg1 = is_if ? o2 : v2;
            const float go1 = is_if ? o3 : v3;

            const int j = (bn >> 2) + warp_n * 8 + nt * 2 + (q >> 1);
            const float c0v0 = c0[(size_t)r * H_DIM + j];
            const float c0v1 = c0[(size_t)(r + 8) * H_DIM + j];

            const float cn0 = sigmoidf_(gf0) * c0v0 + sigmoidf_(gi0) * tanhf(gg0);
            const float cn1 = sigmoidf_(gf1) * c0v1 + sigmoidf_(gi1) * tanhf(gg1);
            const float hn0 = sigmoidf_(go0) * tanhf(cn0);
            const float hn1 = sigmoidf_(go1) * tanhf(cn1);

            if (is_if) {
                out[(size_t)r * H_DIM + j]       = hn0;
                out[(size_t)(r + 8) * H_DIM + j] = hn1;
            } else {
                out[(size_t)B_DIM * H_DIM + (size_t)r * H_DIM + j]       = cn0;
                out[(size_t)B_DIM * H_DIM + (size_t)(r + 8) * H_DIM + j] = cn1;
            }
        }
    }
    #undef LOAD_STAGE
}

// ---------------------------------------------------------------------------
// Launch
// ---------------------------------------------------------------------------
extern "C" void kernel_launch(void* const* d_in, const int* in_sizes, int n_in,
                              void* d_out, int out_size)
{
    const float* x    = (const float*)d_in[0];
    const float* h0   = (const float*)d_in[1];
    const float* c0   = (const float*)d_in[2];
    const float* wih  = (const float*)d_in[3];
    const float* whh  = (const float*)d_in[4];
    const float* b_ih = (const float*)d_in[5];
    const float* b_hh = (const float*)d_in[6];
    float* out = (float*)d_out;

    cudaFuncSetAttribute(lstm_gemm_fused,
                         cudaFuncAttributeMaxDynamicSharedMemorySize, SMEM_TOTAL);

    quantize_rows<<<8208, 256>>>(x, h0, wih, whh, b_ih, b_hh);

    dim3 grid(N_GATES / BN, B_DIM / BM);                 // (64, 32) = 2048 CTAs
    lstm_gemm_fused<<<grid, NTHREADS, SMEM_TOTAL>>>(c0, out);
}

// round 11
// speedup vs baseline: 5.9808x; 5.9808x over previous
#include <cuda_runtime.h>
#include <cuda_fp16.h>
#include <cstdint>

// ---------------------------------------------------------------------------
// Problem constants
// ---------------------------------------------------------------------------
#define B_DIM 4096
#define H_DIM 1024
#define N_GATES 4096       // 4*H
#define K_DIM  2048        // D + H

// GEMM tiling (single-pass fp16 HMMA)
#define BM 128
#define BN 64
#define BK 32              // 32 fp16 = 64 B rows
#define STAGES 6
#define NT (K_DIM / BK)    // 64 k-tiles
#define NTHREADS 256

// smem per stage: A 128x64B + B 64x64B = 12288 B
#define A_TILE_BYTES 8192
#define B_TILE_BYTES 4096
#define STAGE_BYTES (A_TILE_BYTES + B_TILE_BYTES)           // 12288
#define OFF_B A_TILE_BYTES
#define SMEM_TOTAL (STAGES * STAGE_BYTES)                   // 73728 -> 3 CTAs/SM

// ---------------------------------------------------------------------------
// Scratch (device globals). gB/gBias GATE-INTERLEAVED: n' = j*4+g.
// ---------------------------------------------------------------------------
__device__ __half gA[(size_t)B_DIM * K_DIM];
__device__ __half gB[(size_t)N_GATES * K_DIM];
__device__ float gBias[N_GATES];

// ---------------------------------------------------------------------------
// PTX helpers (sm_80+ portable)
// ---------------------------------------------------------------------------
__device__ __forceinline__ uint32_t smem_u32(const void* p) {
    uint32_t a;
    asm("{ .reg .u64 t; cvta.to.shared.u64 t, %1; cvt.u32.u64 %0, t; }" : "=r"(a) : "l"(p));
    return a;
}

#define CP_ASYNC16(dst, src) \
    asm volatile("cp.async.cg.shared.global [%0], [%1], 16;" \
                 :: "r"(dst), "l"(src) : "memory")
#define CP_COMMIT() asm volatile("cp.async.commit_group;" ::: "memory")
#define CP_WAIT(n)  asm volatile("cp.async.wait_group %0;" :: "n"(n) : "memory")

#define LDSM_X4(r, addr) \
    asm volatile("ldmatrix.sync.aligned.m8n8.x4.shared.b16 {%0,%1,%2,%3}, [%4];" \
                 : "=r"((r)[0]), "=r"((r)[1]), "=r"((r)[2]), "=r"((r)[3]) : "r"(addr))

__device__ __forceinline__ void mma_f16(float* d, const uint32_t* a, const uint32_t* b) {
    asm volatile(
        "mma.sync.aligned.m16n8k16.row.col.f32.f16.f16.f32 "
        "{%0,%1,%2,%3}, {%4,%5,%6,%7}, {%8,%9}, {%0,%1,%2,%3};"
        : "+f"(d[0]), "+f"(d[1]), "+f"(d[2]), "+f"(d[3])
        : "r"(a[0]), "r"(a[1]), "r"(a[2]), "r"(a[3]), "r"(b[0]), "r"(b[1]));
}

__device__ __forceinline__ float sigmoidf_(float v) {
    return 1.0f / (1.0f + __expf(-v));
}

// ---------------------------------------------------------------------------
// Conversion kernel:
//   blocks [0, 8192):      A = [x | h0]  -> gA   (row-identity)
//   blocks [8192, 16384):  B = [wih|whh] -> gB   (rows permuted j*4+g)
//   blocks [16384, 16400): permuted bias sum
// ---------------------------------------------------------------------------
__global__ __launch_bounds__(256)
void convert_all(const float* __restrict__ x,   const float* __restrict__ h0,
                 const float* __restrict__ wih, const float* __restrict__ whh,
                 const float* __restrict__ b_ih, const float* __restrict__ b_hh)
{
    const int bid = blockIdx.x;
    const int tid = threadIdx.x;

    if (bid >= 16384) {                       // bias
        const int np = (bid - 16384) * 256 + tid;        // 0..4095
        const int r = ((np & 3) << 10) | (np >> 2);      // orig row g*1024+j
        gBias[np] = b_ih[r] + b_hh[r];
        return;
    }

    const bool isA = (bid < 8192);
    const int idx = (isA ? bid : bid - 8192) * 256 + tid;  // 4-elem group id
    const int row = idx >> 9;                              // output row
    const int col = (idx & 511) << 2;                      // K column

    int srow = row;
    const float *s0, *s1;
    if (isA) { s0 = x; s1 = h0; }
    else     { s0 = wih; s1 = whh; srow = ((row & 3) << 10) | (row >> 2); }

    const float* src = (col < 1024) ? (s0 + (size_t)srow * 1024 + col)
                                    : (s1 + (size_t)srow * 1024 + (col - 1024));
    float4 v = *reinterpret_cast<const float4*>(src);
    __half2 h01 = __floats2half2_rn(v.x, v.y);
    __half2 h23 = __floats2half2_rn(v.z, v.w);
    __half* dst = isA ? gA : gB;
    const size_t o = (size_t)row * K_DIM + col;
    *reinterpret_cast<__half2*>(dst + o)     = h01;
    *reinterpret_cast<__half2*>(dst + o + 2) = h23;
}

// ---------------------------------------------------------------------------
// Fused single-pass fp16 GEMM + LSTM epilogue, 3 CTAs/SM.
//   gates = A @ B^T  (gate-interleaved columns), fp32 accumulate
//   then per (b,j): c = sig(f)*c0 + sig(i)*tanh(g); h = sig(o)*tanh(c)
// SMEM: rows x 4 16B chunks, chunk' = chunk ^ ((row>>1)&3) (conflict-free).
// ---------------------------------------------------------------------------
__global__ __launch_bounds__(NTHREADS, 3)
void lstm_gemm_fused(const float* __restrict__ c0, float* __restrict__ out)
{
    extern __shared__ char smem[];
    const uint32_t sb = smem_u32(smem);
    const int tid  = threadIdx.x;
    const int wid  = tid >> 5;
    const int lane = tid & 31;
    const int warp_m = wid >> 1;    // 0..3
    const int warp_n = wid & 1;     // 0..1

    const int bm = blockIdx.y * BM;
    const int bn = blockIdx.x * BN;

    float acc[2][4][4];
    #pragma unroll
    for (int mt = 0; mt < 2; mt++)
        #pragma unroll
        for (int nt = 0; nt < 4; nt++)
            #pragma unroll
            for (int j = 0; j < 4; j++)
                acc[mt][nt][j] = 0.0f;

    // ---- ldmatrix addressing (same mapping proven in rounds 5-8) ----
    const int a_row = warp_m * 32 + (lane & 15);
    const int s_a   = (a_row >> 1) & 3;
    const int a_c0  = lane >> 4;                              // 0/1
    const int b_row = warp_n * 32 + ((lane >> 4) << 3) + (lane & 7);
    const int s_b   = (b_row >> 1) & 3;
    const int b_c0  = (lane >> 3) & 1;

    // ---- cp.async addressing: 768 chunks/stage, 3 per thread ----
    const int r0 = tid >> 2;                 // 0..63
    const int cc = tid & 3;                  // 16B chunk
    const uint32_t dstoff = (uint32_t)(r0 * 64 + ((cc ^ ((r0 >> 1) & 3)) << 4));
    const __half* pA = gA + (size_t)(bm + r0) * K_DIM + cc * 8;
    const __half* pB = gB + (size_t)(bn + r0) * K_DIM + cc * 8;
    const size_t HSTEP = (size_t)64 * K_DIM;   // +64 rows (A tile second half)

    #define LOAD_STAGE(bufidx, k0) do {                                         \
        const uint32_t s_ = sb + (bufidx) * STAGE_BYTES + dstoff;               \
        CP_ASYNC16(s_,          pA + (k0));                                     \
        CP_ASYNC16(s_ + 4096,   pA + (k0) + HSTEP);                             \
        CP_ASYNC16(s_ + OFF_B,  pB + (k0));                                     \
    } while (0)

    // prologue: stages 0..4
    #pragma unroll
    for (int s = 0; s < STAGES - 1; s++) {
        LOAD_STAGE(s, s * BK);
        CP_COMMIT();
    }

    int cbuf = 0, lbuf = STAGES - 1;
    for (int t = 0; t < NT; t++) {
        CP_WAIT(STAGES - 2);
        __syncthreads();
        if (t + STAGES - 1 < NT)
            LOAD_STAGE(lbuf, (t + STAGES - 1) * BK);
        CP_COMMIT();

        const uint32_t stage = sb + cbuf * STAGE_BYTES;
        #pragma unroll
        for (int ks = 0; ks < 2; ks++) {
            uint32_t a_fr[2][4];
            const int ca = ((ks * 2 + a_c0) ^ s_a) << 4;
            #pragma unroll
            for (int mt = 0; mt < 2; mt++) {
                const uint32_t aa = stage + (a_row + mt * 16) * 64 + ca;
                LDSM_X4(a_fr[mt], aa);
            }
            const int cb = ((ks * 2 + b_c0) ^ s_b) << 4;
            #pragma unroll
            for (int g = 0; g < 2; g++) {
                uint32_t b_fr[4];
                const uint32_t ba = stage + OFF_B + (b_row + g * 16) * 64 + cb;
                LDSM_X4(b_fr, ba);
                #pragma unroll
                for (int mt = 0; mt < 2; mt++)
                    #pragma unroll
                    for (int h = 0; h < 2; h++)
                        mma_f16(acc[mt][g * 2 + h], a_fr[mt], &b_fr[h * 2]);
            }
        }
        if (++cbuf == STAGES) cbuf = 0;
        if (++lbuf == STAGES) lbuf = 0;
    }

    // ---- fused LSTM epilogue ----
    const int q = lane & 3;
    const bool is_if = ((q & 1) == 0);

    float bsum[4][2];
    #pragma unroll
    for (int nt = 0; nt < 4; nt++) {
        const int c = bn + warp_n * 32 + nt * 8 + q * 2;
        bsum[nt][0] = gBias[c];
        bsum[nt][1] = gBias[c + 1];
    }

    #pragma unroll
    for (int mt = 0; mt < 2; mt++) {
        const int r = bm + warp_m * 32 + mt * 16 + (lane >> 2);
        #pragma unroll
        for (int nt = 0; nt < 4; nt++) {
            float v0 = acc[mt][nt][0] + bsum[nt][0];
            float v1 = acc[mt][nt][1] + bsum[nt][1];
            float v2 = acc[mt][nt][2] + bsum[nt][0];
            float v3 = acc[mt][nt][3] + bsum[nt][1];
            const float o0 = __shfl_xor_sync(0xffffffffu, v0, 1);
            const float o1 = __shfl_xor_sync(0xffffffffu, v1, 1);
            const float o2 = __shfl_xor_sync(0xffffffffu, v2, 1);
            const float o3 = __shfl_xor_sync(0xffffffffu, v3, 1);

            const float gi0 = is_if ? v0 : o0;
            const float gf0 = is_if ? v1 : o1;
            const float gg0 = is_if ? o0 : v0;
            const float go0 = is_if ? o1 : v1;
            const float gi1 = is_if ? v2 : o2;
            const float gf1 = is_if ? v3 : o3;
            const float gg1 = is_if ? o2 : v2;
            const float go1 = is_if ? o3 : v3;

            const int j = (bn >> 2) + warp_n * 8 + nt * 2 + (q >> 1);
            const float c0v0 = c0[(size_t)r * H_DIM + j];
            const float c0v1 = c0[(size_t)(r + 8) * H_DIM + j];

            const float cn0 = sigmoidf_(gf0) * c0v0 + sigmoidf_(gi0) * tanhf(gg0);
            const float cn1 = sigmoidf_(gf1) * c0v1 + sigmoidf_(gi1) * tanhf(gg1);
            const float hn0 = sigmoidf_(go0) * tanhf(cn0);
            const float hn1 = sigmoidf_(go1) * tanhf(cn1);

            if (is_if) {
                out[(size_t)r * H_DIM + j]       = hn0;
                out[(size_t)(r + 8) * H_DIM + j] = hn1;
            } else {
                out[(size_t)B_DIM * H_DIM + (size_t)r * H_DIM + j]       = cn0;
                out[(size_t)B_DIM * H_DIM + (size_t)(r + 8) * H_DIM + j] = cn1;
            }
        }
    }
    #undef LOAD_STAGE
}

// ---------------------------------------------------------------------------
// Launch
// ---------------------------------------------------------------------------
extern "C" void kernel_launch(void* const* d_in, const int* in_sizes, int n_in,
                              void* d_out, int out_size)
{
    const float* x    = (const float*)d_in[0];
    const float* h0   = (const float*)d_in[1];
    const float* c0   = (const float*)d_in[2];
    const float* wih  = (const float*)d_in[3];
    const float* whh  = (const float*)d_in[4];
    const float* b_ih = (const float*)d_in[5];
    const float* b_hh = (const float*)d_in[6];
    float* out = (float*)d_out;

    cudaFuncSetAttribute(lstm_gemm_fused,
                         cudaFuncAttributeMaxDynamicSharedMemorySize, SMEM_TOTAL);

    convert_all<<<16400, 256>>>(x, h0, wih, whh, b_ih, b_hh);

    dim3 grid(N_GATES / BN, B_DIM / BM);                 // (64, 32) = 2048 CTAs
    lstm_gemm_fused<<<grid, NTHREADS, SMEM_TOTAL>>>(c0, out);
}

// round 12
// speedup vs baseline: 6.4427x; 1.0772x over previous
#include <cuda_runtime.h>
#include <cuda_fp16.h>
#include <cstdint>

// ---------------------------------------------------------------------------
// Problem constants
// ---------------------------------------------------------------------------
#define B_DIM 4096
#define H_DIM 1024
#define N_GATES 4096       // 4*H
#define K_DIM  2048        // D + H

// GEMM tiling (single-pass fp16 HMMA, 64x32 warp tiles)
#define BM 128
#define BN 128
#define BK 32              // 32 fp16 = 64 B rows
#define STAGES 4
#define NT (K_DIM / BK)    // 64 k-tiles
#define NTHREADS 256

// smem per stage: A 128x64B + B 128x64B = 16384 B
#define A_TILE_BYTES 8192
#define B_TILE_BYTES 8192
#define STAGE_BYTES (A_TILE_BYTES + B_TILE_BYTES)           // 16384
#define OFF_B A_TILE_BYTES
#define SMEM_TOTAL (STAGES * STAGE_BYTES)                   // 65536 -> 2 CTAs/SM

// ---------------------------------------------------------------------------
// Scratch (device globals). gB/gBias GATE-INTERLEAVED: n' = j*4+g.
// ---------------------------------------------------------------------------
__device__ __half gA[(size_t)B_DIM * K_DIM];
__device__ __half gB[(size_t)N_GATES * K_DIM];
__device__ float gBias[N_GATES];

// ---------------------------------------------------------------------------
// PTX helpers (sm_80+ portable)
// ---------------------------------------------------------------------------
__device__ __forceinline__ uint32_t smem_u32(const void* p) {
    uint32_t a;
    asm("{ .reg .u64 t; cvta.to.shared.u64 t, %1; cvt.u32.u64 %0, t; }" : "=r"(a) : "l"(p));
    return a;
}

#define CP_ASYNC16(dst, src) \
    asm volatile("cp.async.cg.shared.global [%0], [%1], 16;" \
                 :: "r"(dst), "l"(src) : "memory")
#define CP_COMMIT() asm volatile("cp.async.commit_group;" ::: "memory")
#define CP_WAIT(n)  asm volatile("cp.async.wait_group %0;" :: "n"(n) : "memory")

#define LDSM_X4(r, addr) \
    asm volatile("ldmatrix.sync.aligned.m8n8.x4.shared.b16 {%0,%1,%2,%3}, [%4];" \
                 : "=r"((r)[0]), "=r"((r)[1]), "=r"((r)[2]), "=r"((r)[3]) : "r"(addr))

__device__ __forceinline__ void mma_f16(float* d, const uint32_t* a, const uint32_t* b) {
    asm volatile(
        "mma.sync.aligned.m16n8k16.row.col.f32.f16.f16.f32 "
        "{%0,%1,%2,%3}, {%4,%5,%6,%7}, {%8,%9}, {%0,%1,%2,%3};"
        : "+f"(d[0]), "+f"(d[1]), "+f"(d[2]), "+f"(d[3])
        : "r"(a[0]), "r"(a[1]), "r"(a[2]), "r"(a[3]), "r"(b[0]), "r"(b[1]));
}

__device__ __forceinline__ float sigmoidf_(float v) {
    return 1.0f / (1.0f + __expf(-v));
}

// ---------------------------------------------------------------------------
// Conversion kernel:
//   blocks [0, 8192):      A = [x | h0]  -> gA   (row-identity)
//   blocks [8192, 16384):  B = [wih|whh] -> gB   (rows permuted j*4+g)
//   blocks [16384, 16400): permuted bias sum
// ---------------------------------------------------------------------------
__global__ __launch_bounds__(256)
void convert_all(const float* __restrict__ x,   const float* __restrict__ h0,
                 const float* __restrict__ wih, const float* __restrict__ whh,
                 const float* __restrict__ b_ih, const float* __restrict__ b_hh)
{
    const int bid = blockIdx.x;
    const int tid = threadIdx.x;

    if (bid >= 16384) {                       // bias
        const int np = (bid - 16384) * 256 + tid;        // 0..4095
        const int r = ((np & 3) << 10) | (np >> 2);      // orig row g*1024+j
        gBias[np] = b_ih[r] + b_hh[r];
        return;
    }

    const bool isA = (bid < 8192);
    const int idx = (isA ? bid : bid - 8192) * 256 + tid;  // 4-elem group id
    const int row = idx >> 9;                              // output row
    const int col = (idx & 511) << 2;                      // K column

    int srow = row;
    const float *s0, *s1;
    if (isA) { s0 = x; s1 = h0; }
    else     { s0 = wih; s1 = whh; srow = ((row & 3) << 10) | (row >> 2); }

    const float* src = (col < 1024) ? (s0 + (size_t)srow * 1024 + col)
                                    : (s1 + (size_t)srow * 1024 + (col - 1024));
    float4 v = *reinterpret_cast<const float4*>(src);
    __half2 h01 = __floats2half2_rn(v.x, v.y);
    __half2 h23 = __floats2half2_rn(v.z, v.w);
    __half* dst = isA ? gA : gB;
    const size_t o = (size_t)row * K_DIM + col;
    *reinterpret_cast<__half2*>(dst + o)     = h01;
    *reinterpret_cast<__half2*>(dst + o + 2) = h23;
}

// ---------------------------------------------------------------------------
// Fused single-pass fp16 GEMM + LSTM epilogue.
//   gates = A @ B^T  (gate-interleaved columns), fp32 accumulate
//   8 warps: warp_m = wid>>2 (2), warp_n = wid&3 (4); warp tile 64x32.
//   FLOP/smem-byte = 21.3 (was 16) -> smem demand ~127 B/cyc at full rate.
// SMEM: rows x 4 16B chunks, chunk' = chunk ^ ((row>>1)&3) (conflict-free).
// ---------------------------------------------------------------------------
__global__ __launch_bounds__(NTHREADS, 2)
void lstm_gemm_fused(const float* __restrict__ c0, float* __restrict__ out)
{
    extern __shared__ char smem[];
    const uint32_t sb = smem_u32(smem);
    const int tid  = threadIdx.x;
    const int wid  = tid >> 5;
    const int lane = tid & 31;
    const int warp_m = wid >> 2;    // 0..1, 64 rows each
    const int warp_n = wid & 3;     // 0..3, 32 cols each

    const int bm = blockIdx.y * BM;
    const int bn = blockIdx.x * BN;

    float acc[4][4][4];             // [mt][nt][frag]
    #pragma unroll
    for (int mt = 0; mt < 4; mt++)
        #pragma unroll
        for (int nt = 0; nt < 4; nt++)
            #pragma unroll
            for (int j = 0; j < 4; j++)
                acc[mt][nt][j] = 0.0f;

    // ---- ldmatrix addressing ----
    const int a_row = warp_m * 64 + (lane & 15);              // + mt*16
    const int s_a   = (a_row >> 1) & 3;
    const int a_c0  = lane >> 4;                              // 0/1
    const int b_row = warp_n * 32 + ((lane >> 4) << 3) + (lane & 7);  // + g*16
    const int s_b   = (b_row >> 1) & 3;
    const int b_c0  = (lane >> 3) & 1;

    // ---- cp.async addressing: A 512 chunks + B 512 chunks, 4 per thread ----
    const int r0 = tid >> 2;                 // 0..63
    const int cc = tid & 3;                  // 16B chunk
    const uint32_t dstoff = (uint32_t)(r0 * 64 + ((cc ^ ((r0 >> 1) & 3)) << 4));
    const __half* pA = gA + (size_t)(bm + r0) * K_DIM + cc * 8;
    const __half* pB = gB + (size_t)(bn + r0) * K_DIM + cc * 8;
    const size_t HSTEP = (size_t)64 * K_DIM;   // +64 rows

    #define LOAD_STAGE(bufidx, k0) do {                                         \
        const uint32_t s_ = sb + (bufidx) * STAGE_BYTES + dstoff;               \
        CP_ASYNC16(s_,                  pA + (k0));                             \
        CP_ASYNC16(s_ + 4096,           pA + (k0) + HSTEP);                     \
        CP_ASYNC16(s_ + OFF_B,          pB + (k0));                             \
        CP_ASYNC16(s_ + OFF_B + 4096,   pB + (k0) + HSTEP);                     \
    } while (0)

    // prologue: stages 0..2
    #pragma unroll
    for (int s = 0; s < STAGES - 1; s++) {
        LOAD_STAGE(s, s * BK);
        CP_COMMIT();
    }

    int cbuf = 0, lbuf = STAGES - 1;
    for (int t = 0; t < NT; t++) {
        CP_WAIT(STAGES - 2);
        __syncthreads();
        if (t + STAGES - 1 < NT)
            LOAD_STAGE(lbuf, (t + STAGES - 1) * BK);
        CP_COMMIT();

        const uint32_t stage = sb + cbuf * STAGE_BYTES;
        #pragma unroll
        for (int ks = 0; ks < 2; ks++) {
            uint32_t a_fr[4][4];
            const int ca = ((ks * 2 + a_c0) ^ s_a) << 4;
            #pragma unroll
            for (int mt = 0; mt < 4; mt++) {
                const uint32_t aa = stage + (a_row + mt * 16) * 64 + ca;
                LDSM_X4(a_fr[mt], aa);
            }
            const int cb = ((ks * 2 + b_c0) ^ s_b) << 4;
            #pragma unroll
            for (int g = 0; g < 2; g++) {
                uint32_t b_fr[4];
                const uint32_t ba = stage + OFF_B + (b_row + g * 16) * 64 + cb;
                LDSM_X4(b_fr, ba);
                #pragma unroll
                for (int mt = 0; mt < 4; mt++)
                    #pragma unroll
                    for (int h = 0; h < 2; h++)
                        mma_f16(acc[mt][g * 2 + h], a_fr[mt], &b_fr[h * 2]);
            }
        }
        if (++cbuf == STAGES) cbuf = 0;
        if (++lbuf == STAGES) lbuf = 0;
    }

    // ---- fused LSTM epilogue ----
    const int q = lane & 3;
    const bool is_if = ((q & 1) == 0);

    float bsum[4][2];
    #pragma unroll
    for (int nt = 0; nt < 4; nt++) {
        const int c = bn + warp_n * 32 + nt * 8 + q * 2;
        bsum[nt][0] = gBias[c];
        bsum[nt][1] = gBias[c + 1];
    }

    #pragma unroll
    for (int mt = 0; mt < 4; mt++) {
        const int r = bm + warp_m * 64 + mt * 16 + (lane >> 2);
        #pragma unroll
        for (int nt = 0; nt < 4; nt++) {
            float v0 = acc[mt][nt][0] + bsum[nt][0];
            float v1 = acc[mt][nt][1] + bsum[nt][1];
            float v2 = acc[mt][nt][2] + bsum[nt][0];
            float v3 = acc[mt][nt][3] + bsum[nt][1];
            const float o0 = __shfl_xor_sync(0xffffffffu, v0, 1);
            const float o1 = __shfl_xor_sync(0xffffffffu, v1, 1);
            const float o2 = __shfl_xor_sync(0xffffffffu, v2, 1);
            const float o3 = __shfl_xor_sync(0xffffffffu, v3, 1);

            const float gi0 = is_if ? v0 : o0;
            const float gf0 = is_if ? v1 : o1;
            const float gg0 = is_if ? o0 : v0;
            const float go0 = is_if ? o1 : v1;
            const float gi1 = is_if ? v2 : o2;
            const float gf1 = is_if ? v3 : o3;
            const float gg1 = is_if ? o2 : v2;
            const float go1 = is_if ? o3 : v3;

            const int j = (bn >> 2) + warp_n * 8 + nt * 2 + (q >> 1);
            const float c0v0 = c0[(size_t)r * H_DIM + j];
            const float c0v1 = c0[(size_t)(r + 8) * H_DIM + j];

            const float cn0 = sigmoidf_(gf0) * c0v0 + sigmoidf_(gi0) * tanhf(gg0);
            const float cn1 = sigmoidf_(gf1) * c0v1 + sigmoidf_(gi1) * tanhf(gg1);
            const float hn0 = sigmoidf_(go0) * tanhf(cn0);
            const float hn1 = sigmoidf_(go1) * tanhf(cn1);

            if (is_if) {
                out[(size_t)r * H_DIM + j]       = hn0;
                out[(size_t)(r + 8) * H_DIM + j] = hn1;
            } else {
                out[(size_t)B_DIM * H_DIM + (size_t)r * H_DIM + j]       = cn0;
                out[(size_t)B_DIM * H_DIM + (size_t)(r + 8) * H_DIM + j] = cn1;
            }
        }
    }
    #undef LOAD_STAGE
}

// ---------------------------------------------------------------------------
// Launch
// ---------------------------------------------------------------------------
extern "C" void kernel_launch(void* const* d_in, const int* in_sizes, int n_in,
                              void* d_out, int out_size)
{
    const float* x    = (const float*)d_in[0];
    const float* h0   = (const float*)d_in[1];
    const float* c0   = (const float*)d_in[2];
    const float* wih  = (const float*)d_in[3];
    const float* whh  = (const float*)d_in[4];
    const float* b_ih = (const float*)d_in[5];
    const float* b_hh = (const float*)d_in[6];
    float* out = (float*)d_out;

    cudaFuncSetAttribute(lstm_gemm_fused,
                         cudaFuncAttributeMaxDynamicSharedMemorySize, SMEM_TOTAL);

    convert_all<<<16400, 256>>>(x, h0, wih, whh, b_ih, b_hh);

    dim3 grid(N_GATES / BN, B_DIM / BM);                 // (32, 32) = 1024 CTAs
    lstm_gemm_fused<<<grid, NTHREADS, SMEM_TOTAL>>>(c0, out);
}

// round 13
// speedup vs baseline: 6.6176x; 1.0271x over previous
#include <cuda_runtime.h>
#include <cuda_fp16.h>
#include <cstdint>

// ---------------------------------------------------------------------------
// Problem constants
// ---------------------------------------------------------------------------
#define B_DIM 4096
#define H_DIM 1024
#define N_GATES 4096       // 4*H
#define K_DIM  2048        // D + H

// GEMM tiling (single-pass fp16 HMMA, 64x32 warp tiles, BK=64)
#define BM 128
#define BN 128
#define BK 64              // 64 fp16 = 128 B rows
#define STAGES 3
#define NT (K_DIM / BK)    // 32 k-tiles
#define NTHREADS 256

// smem per stage: A 128x128B + B 128x128B = 32768 B
#define A_TILE_BYTES 16384
#define B_TILE_BYTES 16384
#define STAGE_BYTES (A_TILE_BYTES + B_TILE_BYTES)           // 32768
#define OFF_B A_TILE_BYTES
#define SMEM_TOTAL (STAGES * STAGE_BYTES)                   // 98304 -> 2 CTAs/SM

// ---------------------------------------------------------------------------
// Scratch (device globals). gB/gBias GATE-INTERLEAVED: n' = j*4+g.
// ---------------------------------------------------------------------------
__device__ __half gA[(size_t)B_DIM * K_DIM];
__device__ __half gB[(size_t)N_GATES * K_DIM];
__device__ float gBias[N_GATES];

// ---------------------------------------------------------------------------
// PTX helpers (sm_80+ portable)
// ---------------------------------------------------------------------------
__device__ __forceinline__ uint32_t smem_u32(const void* p) {
    uint32_t a;
    asm("{ .reg .u64 t; cvta.to.shared.u64 t, %1; cvt.u32.u64 %0, t; }" : "=r"(a) : "l"(p));
    return a;
}

#define CP_ASYNC16(dst, src) \
    asm volatile("cp.async.cg.shared.global [%0], [%1], 16;" \
                 :: "r"(dst), "l"(src) : "memory")
#define CP_COMMIT() asm volatile("cp.async.commit_group;" ::: "memory")
#define CP_WAIT(n)  asm volatile("cp.async.wait_group %0;" :: "n"(n) : "memory")

#define LDSM_X4(r, addr) \
    asm volatile("ldmatrix.sync.aligned.m8n8.x4.shared.b16 {%0,%1,%2,%3}, [%4];" \
                 : "=r"((r)[0]), "=r"((r)[1]), "=r"((r)[2]), "=r"((r)[3]) : "r"(addr))

__device__ __forceinline__ void mma_f16(float* d, const uint32_t* a, const uint32_t* b) {
    asm volatile(
        "mma.sync.aligned.m16n8k16.row.col.f32.f16.f16.f32 "
        "{%0,%1,%2,%3}, {%4,%5,%6,%7}, {%8,%9}, {%0,%1,%2,%3};"
        : "+f"(d[0]), "+f"(d[1]), "+f"(d[2]), "+f"(d[3])
        : "r"(a[0]), "r"(a[1]), "r"(a[2]), "r"(a[3]), "r"(b[0]), "r"(b[1]));
}

__device__ __forceinline__ float sigmoidf_(float v) {
    return 1.0f / (1.0f + __expf(-v));
}

// ---------------------------------------------------------------------------
// Conversion kernel:
//   blocks [0, 8192):      A = [x | h0]  -> gA   (row-identity)
//   blocks [8192, 16384):  B = [wih|whh] -> gB   (rows permuted j*4+g)
//   blocks [16384, 16400): permuted bias sum
// ---------------------------------------------------------------------------
__global__ __launch_bounds__(256)
void convert_all(const float* __restrict__ x,   const float* __restrict__ h0,
                 const float* __restrict__ wih, const float* __restrict__ whh,
                 const float* __restrict__ b_ih, const float* __restrict__ b_hh)
{
    const int bid = blockIdx.x;
    const int tid = threadIdx.x;

    if (bid >= 16384) {                       // bias
        const int np = (bid - 16384) * 256 + tid;        // 0..4095
        const int r = ((np & 3) << 10) | (np >> 2);      // orig row g*1024+j
        gBias[np] = b_ih[r] + b_hh[r];
        return;
    }

    const bool isA = (bid < 8192);
    const int idx = (isA ? bid : bid - 8192) * 256 + tid;  // 4-elem group id
    const int row = idx >> 9;                              // output row
    const int col = (idx & 511) << 2;                      // K column

    int srow = row;
    const float *s0, *s1;
    if (isA) { s0 = x; s1 = h0; }
    else     { s0 = wih; s1 = whh; srow = ((row & 3) << 10) | (row >> 2); }

    const float* src = (col < 1024) ? (s0 + (size_t)srow * 1024 + col)
                                    : (s1 + (size_t)srow * 1024 + (col - 1024));
    float4 v = *reinterpret_cast<const float4*>(src);
    __half2 h01 = __floats2half2_rn(v.x, v.y);
    __half2 h23 = __floats2half2_rn(v.z, v.w);
    __half* dst = isA ? gA : gB;
    const size_t o = (size_t)row * K_DIM + col;
    *reinterpret_cast<__half2*>(dst + o)     = h01;
    *reinterpret_cast<__half2*>(dst + o + 2) = h23;
}

// ---------------------------------------------------------------------------
// Fused single-pass fp16 GEMM + LSTM epilogue.
//   gates = A @ B^T (gate-interleaved cols), fp32 accumulate. BK=64: 32 iters,
//   one barrier per 2048 compute-cycles (fixed overhead amortized 2x vs BK=32).
// SMEM: 128B rows, 8 16B-chunks, chunk' = chunk ^ (row&7) (conflict-free for
//   both cp.async 16B stores and ldmatrix 8-row column reads).
// ---------------------------------------------------------------------------
__global__ __launch_bounds__(NTHREADS, 2)
void lstm_gemm_fused(const float* __restrict__ c0, float* __restrict__ out)
{
    extern __shared__ char smem[];
    const uint32_t sb = smem_u32(smem);
    const int tid  = threadIdx.x;
    const int wid  = tid >> 5;
    const int lane = tid & 31;
    const int warp_m = wid >> 2;    // 0..1, 64 rows each
    const int warp_n = wid & 3;     // 0..3, 32 cols each

    const int bm = blockIdx.y * BM;
    const int bn = blockIdx.x * BN;

    float acc[4][4][4];             // [mt][nt][frag]
    #pragma unroll
    for (int mt = 0; mt < 4; mt++)
        #pragma unroll
        for (int nt = 0; nt < 4; nt++)
            #pragma unroll
            for (int j = 0; j < 4; j++)
                acc[mt][nt][j] = 0.0f;

    // ---- ldmatrix addressing (128B rows, swizzle chunk ^ (row&7)) ----
    const int a_row = warp_m * 64 + (lane & 15);              // + mt*16
    const int s_a   = a_row & 7;                              // invariant mod 16-row step? (mt*16 keeps &7) yes
    const int a_c0  = lane >> 4;                              // 0/1
    const int b_row = warp_n * 32 + ((lane >> 4) << 3) + (lane & 7);  // + g*16
    const int s_b   = b_row & 7;
    const int b_c0  = (lane >> 3) & 1;

    // ---- cp.async: A 1024 chunks + B 1024 chunks, 8 per thread ----
    const int r0 = tid >> 3;                 // 0..31
    const int cc = tid & 7;                  // 16B chunk in 128B row
    const uint32_t dstoff = (uint32_t)(r0 * 128 + ((cc ^ (r0 & 7)) << 4));
    const __half* pA = gA + (size_t)(bm + r0) * K_DIM + cc * 8;
    const __half* pB = gB + (size_t)(bn + r0) * K_DIM + cc * 8;
    const size_t RSTEP = (size_t)32 * K_DIM;   // +32 rows ((r0+32j)&7 == r0&7)

    #define LOAD_STAGE(bufidx, k0) do {                                         \
        const uint32_t s_ = sb + (bufidx) * STAGE_BYTES + dstoff;               \
        CP_ASYNC16(s_,                  pA + (k0));                             \
        CP_ASYNC16(s_ + 4096,           pA + (k0) + RSTEP);                     \
        CP_ASYNC16(s_ + 8192,           pA + (k0) + 2 * RSTEP);                 \
        CP_ASYNC16(s_ + 12288,          pA + (k0) + 3 * RSTEP);                 \
        CP_ASYNC16(s_ + OFF_B,          pB + (k0));                             \
        CP_ASYNC16(s_ + OFF_B + 4096,   pB + (k0) + RSTEP);                     \
        CP_ASYNC16(s_ + OFF_B + 8192,   pB + (k0) + 2 * RSTEP);                 \
        CP_ASYNC16(s_ + OFF_B + 12288,  pB + (k0) + 3 * RSTEP);                 \
    } while (0)

    // prologue: stages 0,1
    LOAD_STAGE(0, 0);
    CP_COMMIT();
    LOAD_STAGE(1, BK);
    CP_COMMIT();

    int cbuf = 0, lbuf = 2;
    for (int t = 0; t < NT; t++) {
        CP_WAIT(1);
        __syncthreads();
        if (t + 2 < NT)
            LOAD_STAGE(lbuf, (t + 2) * BK);
        CP_COMMIT();

        const uint32_t stage = sb + cbuf * STAGE_BYTES;
        #pragma unroll
        for (int ks = 0; ks < 4; ks++) {     // four k16 steps per 128B row
            uint32_t a_fr[4][4];
            const int ca = ((ks * 2 + a_c0) ^ s_a) << 4;
            #pragma unroll
            for (int mt = 0; mt < 4; mt++) {
                const uint32_t aa = stage + (a_row + mt * 16) * 128 + ca;
                LDSM_X4(a_fr[mt], aa);
            }
            const int cb = ((ks * 2 + b_c0) ^ s_b) << 4;
            #pragma unroll
            for (int g = 0; g < 2; g++) {
                uint32_t b_fr[4];
                const uint32_t ba = stage + OFF_B + (b_row + g * 16) * 128 + cb;
                LDSM_X4(b_fr, ba);
                #pragma unroll
                for (int mt = 0; mt < 4; mt++)
                    #pragma unroll
                    for (int h = 0; h < 2; h++)
                        mma_f16(acc[mt][g * 2 + h], a_fr[mt], &b_fr[h * 2]);
            }
        }
        if (++cbuf == STAGES) cbuf = 0;
        if (++lbuf == STAGES) lbuf = 0;
    }

    // ---- fused LSTM epilogue ----
    const int q = lane & 3;
    const bool is_if = ((q & 1) == 0);

    float bsum[4][2];
    #pragma unroll
    for (int nt = 0; nt < 4; nt++) {
        const int c = bn + warp_n * 32 + nt * 8 + q * 2;
        bsum[nt][0] = gBias[c];
        bsum[nt][1] = gBias[c + 1];
    }

    #pragma unroll
    for (int mt = 0; mt < 4; mt++) {
        const int r = bm + warp_m * 64 + mt * 16 + (lane >> 2);
        #pragma unroll
        for (int nt = 0; nt < 4; nt++) {
            float v0 = acc[mt][nt][0] + bsum[nt][0];
            float v1 = acc[mt][nt][1] + bsum[nt][1];
            float v2 = acc[mt][nt][2] + bsum[nt][0];
            float v3 = acc[mt][nt][3] + bsum[nt][1];
            const float o0 = __shfl_xor_sync(0xffffffffu, v0, 1);
            const float o1 = __shfl_xor_sync(0xffffffffu, v1, 1);
            const float o2 = __shfl_xor_sync(0xffffffffu, v2, 1);
            const float o3 = __shfl_xor_sync(0xffffffffu, v3, 1);

            const float gi0 = is_if ? v0 : o0;
            const float gf0 = is_if ? v1 : o1;
            const float gg0 = is_if ? o0 : v0;
            const float go0 = is_if ? o1 : v1;
            const float gi1 = is_if ? v2 : o2;
            const float gf1 = is_if ? v3 : o3;
            const float gg1 = is_if ? o2 : v2;
            const float go1 = is_if ? o3 : v3;

            const int j = (bn >> 2) + warp_n * 8 + nt * 2 + (q >> 1);
            const float c0v0 = c0[(size_t)r * H_DIM + j];
            const float c0v1 = c0[(size_t)(r + 8) * H_DIM + j];

            const float cn0 = sigmoidf_(gf0) * c0v0 + sigmoidf_(gi0) * tanhf(gg0);
            const float cn1 = sigmoidf_(gf1) * c0v1 + sigmoidf_(gi1) * tanhf(gg1);
            const float hn0 = sigmoidf_(go0) * tanhf(cn0);
            const float hn1 = sigmoidf_(go1) * tanhf(cn1);

            if (is_if) {
                out[(size_t)r * H_DIM + j]       = hn0;
                out[(size_t)(r + 8) * H_DIM + j] = hn1;
            } else {
                out[(size_t)B_DIM * H_DIM + (size_t)r * H_DIM + j]       = cn0;
                out[(size_t)B_DIM * H_DIM + (size_t)(r + 8) * H_DIM + j] = cn1;
            }
        }
    }
    #undef LOAD_STAGE
}

// ---------------------------------------------------------------------------
// Launch
// ---------------------------------------------------------------------------
extern "C" void kernel_launch(void* const* d_in, const int* in_sizes, int n_in,
                              void* d_out, int out_size)
{
    const float* x    = (const float*)d_in[0];
    const float* h0   = (const float*)d_in[1];
    const float* c0   = (const float*)d_in[2];
    const float* wih  = (const float*)d_in[3];
    const float* whh  = (const float*)d_in[4];
    const float* b_ih = (const float*)d_in[5];
    const float* b_hh = (const float*)d_in[6];
    float* out = (float*)d_out;

    cudaFuncSetAttribute(lstm_gemm_fused,
                         cudaFuncAttributeMaxDynamicSharedMemorySize, SMEM_TOTAL);

    convert_all<<<16400, 256>>>(x, h0, wih, whh, b_ih, b_hh);

    dim3 grid(N_GATES / BN, B_DIM / BM);                 // (32, 32) = 1024 CTAs
    lstm_gemm_fused<<<grid, NTHREADS, SMEM_TOTAL>>>(c0, out);
}